// round 1
// baseline (speedup 1.0000x reference)
#include <cuda_runtime.h>
#include <cuda_bf16.h>
#include <math.h>

// Problem: B=32, N=1024, D=1024, x f32.
// attn = softmax_j( P @ logP^T ), out = attn @ x, where P = softmax(x, -1).
// cross <= 0 always => exp(cross) safe without max subtraction.

#define BDIM 1024   // both N and D are 1024
#define NB   32

__device__ float g_p  [(size_t)NB * BDIM * BDIM];  // softmax(x)
__device__ float g_lp [(size_t)NB * BDIM * BDIM];  // log_softmax(x)
__device__ float g_e  [(size_t)NB * BDIM * BDIM];  // exp(cross)
__device__ float g_inv[(size_t)NB * BDIM];          // 1 / rowsum(exp(cross))

// ---------------------------------------------------------------------------
// K1: per-row softmax + log-softmax of x. One block per row (32768 rows).
// ---------------------------------------------------------------------------
__global__ __launch_bounds__(256) void softmax_rows(const float* __restrict__ x)
{
    __shared__ float red[32];
    const size_t base = (size_t)blockIdx.x * BDIM;
    const int t = threadIdx.x;

    float4 v = *(const float4*)(x + base + t * 4);

    // ---- block max ----
    float m = fmaxf(fmaxf(v.x, v.y), fmaxf(v.z, v.w));
    #pragma unroll
    for (int o = 16; o; o >>= 1) m = fmaxf(m, __shfl_xor_sync(0xffffffffu, m, o));
    if ((t & 31) == 0) red[t >> 5] = m;
    __syncthreads();
    if (t < 32) {
        float mm = (t < 8) ? red[t] : -3.0e38f;
        #pragma unroll
        for (int o = 4; o; o >>= 1) mm = fmaxf(mm, __shfl_xor_sync(0xffffffffu, mm, o));
        if (t == 0) red[0] = mm;
    }
    __syncthreads();
    m = red[0];
    __syncthreads();

    // ---- block sum of exp ----
    float e0 = __expf(v.x - m), e1 = __expf(v.y - m);
    float e2 = __expf(v.z - m), e3 = __expf(v.w - m);
    float s = (e0 + e1) + (e2 + e3);
    #pragma unroll
    for (int o = 16; o; o >>= 1) s += __shfl_xor_sync(0xffffffffu, s, o);
    if ((t & 31) == 0) red[t >> 5] = s;
    __syncthreads();
    if (t < 32) {
        float ss = (t < 8) ? red[t] : 0.0f;
        #pragma unroll
        for (int o = 4; o; o >>= 1) ss += __shfl_xor_sync(0xffffffffu, ss, o);
        if (t == 0) red[0] = ss;
    }
    __syncthreads();
    const float lZ = logf(red[0]);

    float4 lp;
    lp.x = v.x - m - lZ; lp.y = v.y - m - lZ;
    lp.z = v.z - m - lZ; lp.w = v.w - m - lZ;
    float4 p;
    p.x = __expf(lp.x); p.y = __expf(lp.y);
    p.z = __expf(lp.z); p.w = __expf(lp.w);

    *(float4*)(g_lp + base + t * 4) = lp;
    *(float4*)(g_p  + base + t * 4) = p;
}

// ---------------------------------------------------------------------------
// K2: E = exp( P @ logP^T )  (NT GEMM, 128x128 tile, BK=16, 8x8 per thread)
// grid (8, 8, 32), 256 threads.
// ---------------------------------------------------------------------------
__global__ __launch_bounds__(256) void gemm_cross_exp()
{
    const int b  = blockIdx.z;
    const int i0 = blockIdx.y * 128;
    const int j0 = blockIdx.x * 128;

    const float* __restrict__ A  = g_p  + (size_t)b * BDIM * BDIM + (size_t)i0 * BDIM;
    const float* __restrict__ Bp = g_lp + (size_t)b * BDIM * BDIM + (size_t)j0 * BDIM;

    __shared__ float As[16][128];
    __shared__ float Bs[16][128];

    float acc[8][8];
    #pragma unroll
    for (int r = 0; r < 8; ++r)
        #pragma unroll
        for (int c = 0; c < 8; ++c) acc[r][c] = 0.0f;

    const int tid = threadIdx.x;
    const int tr = (tid >> 4) * 8;
    const int tc = (tid & 15) * 8;

    for (int k0 = 0; k0 < BDIM; k0 += 16) {
        #pragma unroll
        for (int tld = 0; tld < 2; ++tld) {
            const int id  = tid + tld * 256;       // 0..511 -> 512 float4 per operand
            const int row = id >> 2;               // 0..127
            const int c4  = (id & 3) << 2;         // 0,4,8,12
            float4 va = *(const float4*)(A  + (size_t)row * BDIM + k0 + c4);
            float4 vb = *(const float4*)(Bp + (size_t)row * BDIM + k0 + c4);
            As[c4 + 0][row] = va.x; As[c4 + 1][row] = va.y;
            As[c4 + 2][row] = va.z; As[c4 + 3][row] = va.w;
            Bs[c4 + 0][row] = vb.x; Bs[c4 + 1][row] = vb.y;
            Bs[c4 + 2][row] = vb.z; Bs[c4 + 3][row] = vb.w;
        }
        __syncthreads();

        #pragma unroll
        for (int k = 0; k < 16; ++k) {
            float a[8], bb[8];
            *(float4*)(a)      = *(const float4*)&As[k][tr];
            *(float4*)(a + 4)  = *(const float4*)&As[k][tr + 4];
            *(float4*)(bb)     = *(const float4*)&Bs[k][tc];
            *(float4*)(bb + 4) = *(const float4*)&Bs[k][tc + 4];
            #pragma unroll
            for (int r = 0; r < 8; ++r)
                #pragma unroll
                for (int c = 0; c < 8; ++c)
                    acc[r][c] = fmaf(a[r], bb[c], acc[r][c]);
        }
        __syncthreads();
    }

    float* __restrict__ C = g_e + (size_t)b * BDIM * BDIM + (size_t)i0 * BDIM + j0;
    #pragma unroll
    for (int r = 0; r < 8; ++r) {
        #pragma unroll
        for (int c4 = 0; c4 < 8; c4 += 4) {
            float4 o;
            o.x = __expf(acc[r][c4 + 0]);
            o.y = __expf(acc[r][c4 + 1]);
            o.z = __expf(acc[r][c4 + 2]);
            o.w = __expf(acc[r][c4 + 3]);
            *(float4*)(C + (size_t)(tr + r) * BDIM + tc + c4) = o;
        }
    }
}

// ---------------------------------------------------------------------------
// K3: g_inv[row] = 1 / sum_j E[row][j].  One block per row.
// ---------------------------------------------------------------------------
__global__ __launch_bounds__(256) void row_inv()
{
    __shared__ float red[32];
    const size_t base = (size_t)blockIdx.x * BDIM;
    const int t = threadIdx.x;

    float4 v = *(const float4*)(g_e + base + t * 4);
    float s = (v.x + v.y) + (v.z + v.w);
    #pragma unroll
    for (int o = 16; o; o >>= 1) s += __shfl_xor_sync(0xffffffffu, s, o);
    if ((t & 31) == 0) red[t >> 5] = s;
    __syncthreads();
    if (t < 32) {
        float ss = (t < 8) ? red[t] : 0.0f;
        #pragma unroll
        for (int o = 4; o; o >>= 1) ss += __shfl_xor_sync(0xffffffffu, ss, o);
        if (t == 0) g_inv[blockIdx.x] = 1.0f / ss;
    }
}

// ---------------------------------------------------------------------------
// K4: out = (E @ x) * inv_rowsum   (NN GEMM, same tiling)
// ---------------------------------------------------------------------------
__global__ __launch_bounds__(256) void gemm_out(const float* __restrict__ x,
                                                float* __restrict__ out)
{
    const int b  = blockIdx.z;
    const int i0 = blockIdx.y * 128;
    const int d0 = blockIdx.x * 128;

    const float* __restrict__ A  = g_e + (size_t)b * BDIM * BDIM + (size_t)i0 * BDIM;
    const float* __restrict__ Xb = x   + (size_t)b * BDIM * BDIM;

    __shared__ float As[16][128];
    __shared__ float Bs[16][128];

    float acc[8][8];
    #pragma unroll
    for (int r = 0; r < 8; ++r)
        #pragma unroll
        for (int c = 0; c < 8; ++c) acc[r][c] = 0.0f;

    const int tid = threadIdx.x;
    const int tr = (tid >> 4) * 8;
    const int tc = (tid & 15) * 8;

    for (int k0 = 0; k0 < BDIM; k0 += 16) {
        // A tile: rows i0..i0+127, cols k0..k0+15 (transpose into k-major)
        #pragma unroll
        for (int tld = 0; tld < 2; ++tld) {
            const int id  = tid + tld * 256;
            const int row = id >> 2;
            const int c4  = (id & 3) << 2;
            float4 va = *(const float4*)(A + (size_t)row * BDIM + k0 + c4);
            As[c4 + 0][row] = va.x; As[c4 + 1][row] = va.y;
            As[c4 + 2][row] = va.z; As[c4 + 3][row] = va.w;
        }
        // B tile: rows k0..k0+15 of x, cols d0..d0+127 (already k-major)
        #pragma unroll
        for (int tld = 0; tld < 2; ++tld) {
            const int id  = tid + tld * 256;
            const int row = id >> 5;               // 0..15
            const int c4  = (id & 31) << 2;        // 0..124
            float4 vb = *(const float4*)(Xb + (size_t)(k0 + row) * BDIM + d0 + c4);
            *(float4*)&Bs[row][c4] = vb;
        }
        __syncthreads();

        #pragma unroll
        for (int k = 0; k < 16; ++k) {
            float a[8], bb[8];
            *(float4*)(a)      = *(const float4*)&As[k][tr];
            *(float4*)(a + 4)  = *(const float4*)&As[k][tr + 4];
            *(float4*)(bb)     = *(const float4*)&Bs[k][tc];
            *(float4*)(bb + 4) = *(const float4*)&Bs[k][tc + 4];
            #pragma unroll
            for (int r = 0; r < 8; ++r)
                #pragma unroll
                for (int c = 0; c < 8; ++c)
                    acc[r][c] = fmaf(a[r], bb[c], acc[r][c]);
        }
        __syncthreads();
    }

    float* __restrict__ C = out + (size_t)b * BDIM * BDIM + (size_t)i0 * BDIM + d0;
    #pragma unroll
    for (int r = 0; r < 8; ++r) {
        const float inv = g_inv[b * BDIM + i0 + tr + r];
        #pragma unroll
        for (int c4 = 0; c4 < 8; c4 += 4) {
            float4 o;
            o.x = acc[r][c4 + 0] * inv;
            o.y = acc[r][c4 + 1] * inv;
            o.z = acc[r][c4 + 2] * inv;
            o.w = acc[r][c4 + 3] * inv;
            *(float4*)(C + (size_t)(tr + r) * BDIM + tc + c4) = o;
        }
    }
}

// ---------------------------------------------------------------------------
extern "C" void kernel_launch(void* const* d_in, const int* in_sizes, int n_in,
                              void* d_out, int out_size)
{
    const float* x = (const float*)d_in[0];
    float* out = (float*)d_out;

    softmax_rows<<<NB * BDIM, 256>>>(x);

    dim3 g(8, 8, NB);
    gemm_cross_exp<<<g, 256>>>();
    row_inv<<<NB * BDIM, 256>>>();
    gemm_out<<<g, 256>>>(x, out);
}